// round 14
// baseline (speedup 1.0000x reference)
#include <cuda_runtime.h>

// Detail loss, simplified:
//   D = sum_c (infer - ref)   per image plane
//   out = (sum|D[w+1]-D[w-1]| + sum|D[h+1]-D[h-1]|) * 0.25 / (98*258*256)
// R13 structure (best: 5.32 TB/s at the 154MB byte floor) plus L2 PREFETCH:
//  - 8 cols/lane, warp-per-(16-row x 256-col) tile, 12 LDG.128 per row
//  - two live row buffers (one-row-ahead LDG pipeline)
//  - serpentine strip walk (halo rows -> L2 hits, DRAM at byte floor)
//  - single wave (1568 warps, regs capped 128 -> 16 w/SM capacity)
//  - NEW: prefetch.global.L2 for row g+3*dir, 1 lane per 128B line.
//    Fire-and-forget: no registers, no scoreboard. Demand LDGs (issued one
//    iteration later) hit L2 (~250cyc) instead of DRAM (~600+cyc queueing),
//    un-exposing the latency that capped issue at 13.6%.

#define NIMG   98            // 2*7*7
#define IMG_H  256
#define IMG_W  256
#define RSTRIP 16            // rows per warp tile
#define VSTRIPS (IMG_H / RSTRIP)         // 16
#define NWARPS (NIMG * VSTRIPS)          // 1568
#define WPB    2
#define NBLOCKS (NWARPS / WPB)           // 784
#define PLANE  (IMG_H * IMG_W)

__device__ float        g_partials[NWARPS];
__device__ unsigned int g_count;     // zero-init; reset each launch by last block

struct Raw {
    float4 a[6];   // infer: 3 channels x 2 float4
    float4 b[6];   // ref
};

__device__ __forceinline__ void issue_load(const float* __restrict__ pi,
                                           const float* __restrict__ pr,
                                           int row, int lane, bool valid, Raw& r) {
    if (valid) {
        const size_t off = (size_t)row * IMG_W + lane * 8;
        #pragma unroll
        for (int c = 0; c < 3; c++) {
            const float* a = pi + (size_t)c * PLANE + off;
            const float* b = pr + (size_t)c * PLANE + off;
            r.a[c * 2]     = *(const float4*)a;
            r.a[c * 2 + 1] = *(const float4*)(a + 4);
            r.b[c * 2]     = *(const float4*)b;
            r.b[c * 2 + 1] = *(const float4*)(b + 4);
        }
    } else {
        const float4 z = make_float4(0.f, 0.f, 0.f, 0.f);
        #pragma unroll
        for (int i = 0; i < 6; i++) { r.a[i] = z; r.b[i] = z; }
    }
}

// Prefetch one row (6 plane chunks) into L2. One lane per 128B line:
// lanes 0,4,8,...,28 each cover one line of the warp's 1KB-per-plane span.
__device__ __forceinline__ void prefetch_row(const float* __restrict__ pi,
                                             const float* __restrict__ pr,
                                             int row, int lane, bool valid) {
    if (valid && (lane & 3) == 0) {
        const size_t off = (size_t)row * IMG_W + lane * 8;
        #pragma unroll
        for (int c = 0; c < 3; c++) {
            asm volatile("prefetch.global.L2 [%0];" ::
                         "l"(pi + (size_t)c * PLANE + off));
            asm volatile("prefetch.global.L2 [%0];" ::
                         "l"(pr + (size_t)c * PLANE + off));
        }
    }
}

__device__ __forceinline__ void combine(const Raw& r, float d[8]) {
    #pragma unroll
    for (int j = 0; j < 8; j++) d[j] = 0.f;
    #pragma unroll
    for (int c = 0; c < 3; c++) {
        const float4 a0 = r.a[c * 2], a1 = r.a[c * 2 + 1];
        const float4 b0 = r.b[c * 2], b1 = r.b[c * 2 + 1];
        d[0] += a0.x - b0.x;  d[1] += a0.y - b0.y;
        d[2] += a0.z - b0.z;  d[3] += a0.w - b0.w;
        d[4] += a1.x - b1.x;  d[5] += a1.y - b1.y;
        d[6] += a1.z - b1.z;  d[7] += a1.w - b1.w;
    }
}

__global__ void __launch_bounds__(WPB * 32, 8)
detail_kernel(const float* __restrict__ infer, const float* __restrict__ ref,
              float* __restrict__ out) {
    const int tid   = threadIdx.x;
    const int lane  = tid & 31;
    const int gw    = blockIdx.x * WPB + (tid >> 5);   // global warp id
    const int n     = gw >> 4;                          // / VSTRIPS
    const int strip = gw & 15;
    const int r0    = strip * RSTRIP;

    // Serpentine: even strips walk top->bottom, odd strips bottom->top, so
    // rows shared across a strip boundary are read at the same time (L2 hit).
    const int dir    = (strip & 1) ? -1 : 1;
    const int gstart = (strip & 1) ? (r0 + RSTRIP - 1) : r0;

    const float* pi = infer + (size_t)n * 3 * PLANE;
    const float* pr = ref   + (size_t)n * 3 * PLANE;

    // Prologue: rows gstart-dir, gstart combined now; row gstart+dir in flight.
    Raw buf[2], rtop, rcur;
    {
        const int rA = gstart - dir;
        issue_load(pi, pr, rA, lane, (unsigned)rA < IMG_H, rtop);
    }
    issue_load(pi, pr, gstart,       lane, true, rcur);
    issue_load(pi, pr, gstart + dir, lane, true, buf[1]);   // consumed at h=0
    {   // warm L2 for the first two pipeline rows
        const int p2 = gstart + 2 * dir;
        const int p3 = gstart + 3 * dir;
        prefetch_row(pi, pr, p2, lane, (unsigned)p2 < IMG_H);
        prefetch_row(pi, pr, p3, lane, (unsigned)p3 < IMG_H);
    }

    float pm[8], pc[8], pn[8];        // rows g-dir, g, g+dir
    combine(rtop, pm);
    combine(rcur, pc);

    float sum = 0.f;

    #pragma unroll 2
    for (int h = 0; h < RSTRIP; h++) {
        const int g = gstart + h * dir;

        // Prefetch row g+4*dir into L2 (its demand LDGs issue 2 iterations on).
        const int rpf = g + 4 * dir;
        prefetch_row(pi, pr, rpf, lane,
                     (h + 3 < RSTRIP) && ((unsigned)rpf < IMG_H));

        // Issue loads for row g+2*dir BEFORE consuming row g+dir (one-ahead,
        // two live buffers -> ~24 LDG.128 in flight per warp).
        const int rnext = g + 2 * dir;
        issue_load(pi, pr, rnext, lane,
                   (h + 1 < RSTRIP) && ((unsigned)rnext < IMG_H), buf[h & 1]);

        combine(buf[(h + 1) & 1], pn);   // row g+dir, issued last iteration

        // Horizontal gradient on row g (values in pc; 8 cols per lane).
        float l = __shfl_up_sync(0xffffffffu,  pc[7], 1);
        float r = __shfl_down_sync(0xffffffffu, pc[0], 1);
        if (lane == 0)  l = 0.f;   // image edge: zero padding
        if (lane == 31) r = 0.f;
        sum += fabsf(pc[1] - l);
        #pragma unroll
        for (int j = 1; j < 7; j++) sum += fabsf(pc[j + 1] - pc[j - 1]);
        sum += fabsf(r - pc[6]);

        // Vertical gradient: |D[g+dir]-D[g-dir]| = |D[g+1]-D[g-1]|.
        #pragma unroll
        for (int j = 0; j < 8; j++) sum += fabsf(pn[j] - pm[j]);

        // Roll the window.
        #pragma unroll
        for (int j = 0; j < 8; j++) { pm[j] = pc[j]; pc[j] = pn[j]; }
    }

    // Warp reduction.
    #pragma unroll
    for (int off = 16; off > 0; off >>= 1)
        sum += __shfl_down_sync(0xffffffffu, sum, off);

    __shared__ bool is_last;
    if (lane == 0) {
        g_partials[gw] = sum;
        __threadfence();
    }
    __syncthreads();
    if (tid == 0)
        is_last = (atomicAdd(&g_count, 1u) == NBLOCKS - 1);
    __syncthreads();

    if (is_last) {
        float t = 0.f;
        #pragma unroll 4
        for (int i = tid; i < NWARPS; i += WPB * 32)
            t += __ldcg(&g_partials[i]);
        #pragma unroll
        for (int off = 16; off > 0; off >>= 1)
            t += __shfl_down_sync(0xffffffffu, t, off);
        __shared__ float wsum[WPB];
        if (lane == 0) wsum[tid >> 5] = t;
        __syncthreads();
        if (tid == 0) {
            float u = 0.f;
            #pragma unroll
            for (int i = 0; i < WPB; i++) u += wsum[i];
            // 0.5 (gradient coeff) * 0.5 (avg of two losses) / (98*258*256)
            out[0] = u * (0.25f / 6472704.0f);
            g_count = 0;   // deterministic across graph replays
        }
    }
}

extern "C" void kernel_launch(void* const* d_in, const int* in_sizes, int n_in,
                              void* d_out, int out_size) {
    const float* infer = (const float*)d_in[0];
    const float* ref   = (const float*)d_in[1];
    detail_kernel<<<NBLOCKS, WPB * 32>>>(infer, ref, (float*)d_out);
}

// round 15
// speedup vs baseline: 1.0587x; 1.0587x over previous
#include <cuda_runtime.h>

// Detail loss, simplified:
//   D = sum_c (infer - ref)   per image plane
//   out = (sum|D[w+1]-D[w-1]| + sum|D[h+1]-D[h-1]|) * 0.25 / (98*258*256)
// R13 structure (8 cols/lane, two live row buffers, serpentine strips) plus
// PERFECT SM BALANCE: 24 strips/image (16x11 + 8x10 rows) -> 2352 work warps,
// launched as 1184 blocks (=148*8) x 2 warps so every SM holds exactly 8
// blocks. R13's 5-vs-6 blocks/SM imbalance (13%) set the wall time.

#define NIMG   98            // 2*7*7
#define IMG_H  256
#define IMG_W  256
#define SPI    24                         // strips per image: 16x11 + 8x10
#define NWORK  (NIMG * SPI)               // 2352 active warps
#define WPB    2
#define NBLOCKS 1184                      // 148 SMs * 8 blocks
#define NWARPS_T (NBLOCKS * WPB)          // 2368 slots (16 idle)
#define PLANE  (IMG_H * IMG_W)

__device__ float        g_partials[NWARPS_T];
__device__ unsigned int g_count;     // zero-init; reset each launch by last block

struct Raw {
    float4 a[6];   // infer: 3 channels x 2 float4
    float4 b[6];   // ref
};

__device__ __forceinline__ void issue_load(const float* __restrict__ pi,
                                           const float* __restrict__ pr,
                                           int row, int lane, bool valid, Raw& r) {
    if (valid) {
        const size_t off = (size_t)row * IMG_W + lane * 8;
        #pragma unroll
        for (int c = 0; c < 3; c++) {
            const float* a = pi + (size_t)c * PLANE + off;
            const float* b = pr + (size_t)c * PLANE + off;
            r.a[c * 2]     = *(const float4*)a;
            r.a[c * 2 + 1] = *(const float4*)(a + 4);
            r.b[c * 2]     = *(const float4*)b;
            r.b[c * 2 + 1] = *(const float4*)(b + 4);
        }
    } else {
        const float4 z = make_float4(0.f, 0.f, 0.f, 0.f);
        #pragma unroll
        for (int i = 0; i < 6; i++) { r.a[i] = z; r.b[i] = z; }
    }
}

__device__ __forceinline__ void combine(const Raw& r, float d[8]) {
    #pragma unroll
    for (int j = 0; j < 8; j++) d[j] = 0.f;
    #pragma unroll
    for (int c = 0; c < 3; c++) {
        const float4 a0 = r.a[c * 2], a1 = r.a[c * 2 + 1];
        const float4 b0 = r.b[c * 2], b1 = r.b[c * 2 + 1];
        d[0] += a0.x - b0.x;  d[1] += a0.y - b0.y;
        d[2] += a0.z - b0.z;  d[3] += a0.w - b0.w;
        d[4] += a1.x - b1.x;  d[5] += a1.y - b1.y;
        d[6] += a1.z - b1.z;  d[7] += a1.w - b1.w;
    }
}

__global__ void __launch_bounds__(WPB * 32, 8)
detail_kernel(const float* __restrict__ infer, const float* __restrict__ ref,
              float* __restrict__ out) {
    const int tid   = threadIdx.x;
    const int lane  = tid & 31;
    const int gw    = blockIdx.x * WPB + (tid >> 5);   // global warp id

    float sum = 0.f;

    if (gw < NWORK) {
        const int n = gw / SPI;
        const int s = gw - n * SPI;
        // Strip geometry: strips 0..15 have 11 rows, strips 16..23 have 10.
        const int start = (s < 16) ? s * 11 : 176 + (s - 16) * 10;
        const int len   = (s < 16) ? 11 : 10;

        // Serpentine: odd strips walk bottom->top so strip-boundary rows are
        // read by both neighbors at the same time (L2 hit; DRAM at byte floor).
        const int dir    = (s & 1) ? -1 : 1;
        const int gstart = (s & 1) ? (start + len - 1) : start;

        const float* pi = infer + (size_t)n * 3 * PLANE;
        const float* pr = ref   + (size_t)n * 3 * PLANE;

        // Prologue: rows gstart-dir, gstart combined now; gstart+dir in flight.
        Raw buf[2], rtop, rcur;
        {
            const int rA = gstart - dir;
            issue_load(pi, pr, rA, lane, (unsigned)rA < IMG_H, rtop);
        }
        issue_load(pi, pr, gstart, lane, true, rcur);
        {
            const int rB = gstart + dir;
            issue_load(pi, pr, rB, lane, (unsigned)rB < IMG_H, buf[1]);
        }

        float pm[8], pc[8], pn[8];        // rows g-dir, g, g+dir
        combine(rtop, pm);
        combine(rcur, pc);

        #pragma unroll 2
        for (int h = 0; h < len; h++) {
            const int g = gstart + h * dir;

            // Issue loads for row g+2*dir BEFORE consuming row g+dir
            // (one-ahead, two live buffers -> ~24 LDG.128 in flight per warp).
            const int rnext = g + 2 * dir;
            issue_load(pi, pr, rnext, lane,
                       (h + 1 < len) && ((unsigned)rnext < IMG_H), buf[h & 1]);

            combine(buf[(h + 1) & 1], pn);   // row g+dir, issued last iteration

            // Horizontal gradient on row g (values in pc; 8 cols per lane).
            float l = __shfl_up_sync(0xffffffffu,  pc[7], 1);
            float r = __shfl_down_sync(0xffffffffu, pc[0], 1);
            if (lane == 0)  l = 0.f;   // image edge: zero padding
            if (lane == 31) r = 0.f;
            sum += fabsf(pc[1] - l);
            #pragma unroll
            for (int j = 1; j < 7; j++) sum += fabsf(pc[j + 1] - pc[j - 1]);
            sum += fabsf(r - pc[6]);

            // Vertical gradient: |D[g+dir]-D[g-dir]| = |D[g+1]-D[g-1]|.
            #pragma unroll
            for (int j = 0; j < 8; j++) sum += fabsf(pn[j] - pm[j]);

            // Roll the window.
            #pragma unroll
            for (int j = 0; j < 8; j++) { pm[j] = pc[j]; pc[j] = pn[j]; }
        }
    }

    // Warp reduction (idle warps contribute 0).
    #pragma unroll
    for (int off = 16; off > 0; off >>= 1)
        sum += __shfl_down_sync(0xffffffffu, sum, off);

    __shared__ bool is_last;
    if (lane == 0) {
        g_partials[gw] = sum;
        __threadfence();
    }
    __syncthreads();
    if (tid == 0)
        is_last = (atomicAdd(&g_count, 1u) == NBLOCKS - 1);
    __syncthreads();

    if (is_last) {
        float t = 0.f;
        #pragma unroll 4
        for (int i = tid; i < NWARPS_T; i += WPB * 32)
            t += __ldcg(&g_partials[i]);
        #pragma unroll
        for (int off = 16; off > 0; off >>= 1)
            t += __shfl_down_sync(0xffffffffu, t, off);
        __shared__ float wsum[WPB];
        if (lane == 0) wsum[tid >> 5] = t;
        __syncthreads();
        if (tid == 0) {
            float u = 0.f;
            #pragma unroll
            for (int i = 0; i < WPB; i++) u += wsum[i];
            // 0.5 (gradient coeff) * 0.5 (avg of two losses) / (98*258*256)
            out[0] = u * (0.25f / 6472704.0f);
            g_count = 0;   // deterministic across graph replays
        }
    }
}

extern "C" void kernel_launch(void* const* d_in, const int* in_sizes, int n_in,
                              void* d_out, int out_size) {
    const float* infer = (const float*)d_in[0];
    const float* ref   = (const float*)d_in[1];
    detail_kernel<<<NBLOCKS, WPB * 32>>>(infer, ref, (float*)d_out);
}

// round 16
// speedup vs baseline: 1.1292x; 1.0667x over previous
#include <cuda_runtime.h>

// Detail loss, simplified:
//   D = sum_c (infer - ref)   per image plane
//   out = (sum|D[w+1]-D[w-1]| + sum|D[h+1]-D[h-1]|) * 0.25 / (98*258*256)
// R13 (best: 5.32 TB/s at the 154MB byte floor) with 256-BIT LOADS:
//  - 8 cols/lane, warp-per-(16-row x 256-col) tile
//  - 6x LDG.256 (ld.global.nc.v8.f32, sm_100+) per row instead of 12x LDG.128:
//    halves LDG count and L1tex wavefront-queue entries per byte; 1KB bursts
//    per warp-request improve DRAM scheduler locality
//  - two live row buffers (one-row-ahead pipeline)
//  - serpentine strip walk (halo rows -> L2 hits, DRAM at byte floor)
//  - single wave (1568 warps, regs capped 128 -> 16 w/SM capacity)

#define NIMG   98            // 2*7*7
#define IMG_H  256
#define IMG_W  256
#define RSTRIP 16            // rows per warp tile
#define VSTRIPS (IMG_H / RSTRIP)         // 16
#define NWARPS (NIMG * VSTRIPS)          // 1568
#define WPB    2
#define NBLOCKS (NWARPS / WPB)           // 784
#define PLANE  (IMG_H * IMG_W)

__device__ float        g_partials[NWARPS];
__device__ unsigned int g_count;     // zero-init; reset each launch by last block

struct Raw {
    float4 a[6];   // infer: 3 channels x 2 float4
    float4 b[6];   // ref
};

// 256-bit global load (Blackwell): 8 consecutive floats, 32B-aligned.
__device__ __forceinline__ void ldg256(const float* __restrict__ p,
                                       float4& lo, float4& hi) {
    asm volatile("ld.global.nc.v8.f32 {%0,%1,%2,%3,%4,%5,%6,%7}, [%8];"
                 : "=f"(lo.x), "=f"(lo.y), "=f"(lo.z), "=f"(lo.w),
                   "=f"(hi.x), "=f"(hi.y), "=f"(hi.z), "=f"(hi.w)
                 : "l"(p));
}

__device__ __forceinline__ void issue_load(const float* __restrict__ pi,
                                           const float* __restrict__ pr,
                                           int row, int lane, bool valid, Raw& r) {
    if (valid) {
        const size_t off = (size_t)row * IMG_W + lane * 8;   // 32B aligned
        #pragma unroll
        for (int c = 0; c < 3; c++) {
            ldg256(pi + (size_t)c * PLANE + off, r.a[c * 2], r.a[c * 2 + 1]);
            ldg256(pr + (size_t)c * PLANE + off, r.b[c * 2], r.b[c * 2 + 1]);
        }
    } else {
        const float4 z = make_float4(0.f, 0.f, 0.f, 0.f);
        #pragma unroll
        for (int i = 0; i < 6; i++) { r.a[i] = z; r.b[i] = z; }
    }
}

__device__ __forceinline__ void combine(const Raw& r, float d[8]) {
    #pragma unroll
    for (int j = 0; j < 8; j++) d[j] = 0.f;
    #pragma unroll
    for (int c = 0; c < 3; c++) {
        const float4 a0 = r.a[c * 2], a1 = r.a[c * 2 + 1];
        const float4 b0 = r.b[c * 2], b1 = r.b[c * 2 + 1];
        d[0] += a0.x - b0.x;  d[1] += a0.y - b0.y;
        d[2] += a0.z - b0.z;  d[3] += a0.w - b0.w;
        d[4] += a1.x - b1.x;  d[5] += a1.y - b1.y;
        d[6] += a1.z - b1.z;  d[7] += a1.w - b1.w;
    }
}

__global__ void __launch_bounds__(WPB * 32, 8)
detail_kernel(const float* __restrict__ infer, const float* __restrict__ ref,
              float* __restrict__ out) {
    const int tid   = threadIdx.x;
    const int lane  = tid & 31;
    const int gw    = blockIdx.x * WPB + (tid >> 5);   // global warp id
    const int n     = gw >> 4;                          // / VSTRIPS
    const int strip = gw & 15;
    const int r0    = strip * RSTRIP;

    // Serpentine: even strips walk top->bottom, odd strips bottom->top, so
    // rows shared across a strip boundary are read at the same time (L2 hit).
    const int dir    = (strip & 1) ? -1 : 1;
    const int gstart = (strip & 1) ? (r0 + RSTRIP - 1) : r0;

    const float* pi = infer + (size_t)n * 3 * PLANE;
    const float* pr = ref   + (size_t)n * 3 * PLANE;

    // Prologue: rows gstart-dir, gstart combined now; row gstart+dir in flight.
    Raw buf[2], rtop, rcur;
    {
        const int rA = gstart - dir;
        issue_load(pi, pr, rA, lane, (unsigned)rA < IMG_H, rtop);
    }
    issue_load(pi, pr, gstart,       lane, true, rcur);
    issue_load(pi, pr, gstart + dir, lane, true, buf[1]);   // consumed at h=0

    float pm[8], pc[8], pn[8];        // rows g-dir, g, g+dir
    combine(rtop, pm);
    combine(rcur, pc);

    float sum = 0.f;

    #pragma unroll 2
    for (int h = 0; h < RSTRIP; h++) {
        const int g = gstart + h * dir;

        // Issue loads for row g+2*dir BEFORE consuming row g+dir (one-ahead,
        // two live buffers -> ~12 LDG.256 in flight per warp).
        const int rnext = g + 2 * dir;
        issue_load(pi, pr, rnext, lane,
                   (h + 1 < RSTRIP) && ((unsigned)rnext < IMG_H), buf[h & 1]);

        combine(buf[(h + 1) & 1], pn);   // row g+dir, issued last iteration

        // Horizontal gradient on row g (values in pc; 8 cols per lane).
        float l = __shfl_up_sync(0xffffffffu,  pc[7], 1);
        float r = __shfl_down_sync(0xffffffffu, pc[0], 1);
        if (lane == 0)  l = 0.f;   // image edge: zero padding
        if (lane == 31) r = 0.f;
        sum += fabsf(pc[1] - l);
        #pragma unroll
        for (int j = 1; j < 7; j++) sum += fabsf(pc[j + 1] - pc[j - 1]);
        sum += fabsf(r - pc[6]);

        // Vertical gradient: |D[g+dir]-D[g-dir]| = |D[g+1]-D[g-1]|.
        #pragma unroll
        for (int j = 0; j < 8; j++) sum += fabsf(pn[j] - pm[j]);

        // Roll the window.
        #pragma unroll
        for (int j = 0; j < 8; j++) { pm[j] = pc[j]; pc[j] = pn[j]; }
    }

    // Warp reduction.
    #pragma unroll
    for (int off = 16; off > 0; off >>= 1)
        sum += __shfl_down_sync(0xffffffffu, sum, off);

    __shared__ bool is_last;
    if (lane == 0) {
        g_partials[gw] = sum;
        __threadfence();
    }
    __syncthreads();
    if (tid == 0)
        is_last = (atomicAdd(&g_count, 1u) == NBLOCKS - 1);
    __syncthreads();

    if (is_last) {
        float t = 0.f;
        #pragma unroll 4
        for (int i = tid; i < NWARPS; i += WPB * 32)
            t += __ldcg(&g_partials[i]);
        #pragma unroll
        for (int off = 16; off > 0; off >>= 1)
            t += __shfl_down_sync(0xffffffffu, t, off);
        __shared__ float wsum[WPB];
        if (lane == 0) wsum[tid >> 5] = t;
        __syncthreads();
        if (tid == 0) {
            float u = 0.f;
            #pragma unroll
            for (int i = 0; i < WPB; i++) u += wsum[i];
            // 0.5 (gradient coeff) * 0.5 (avg of two losses) / (98*258*256)
            out[0] = u * (0.25f / 6472704.0f);
            g_count = 0;   // deterministic across graph replays
        }
    }
}

extern "C" void kernel_launch(void* const* d_in, const int* in_sizes, int n_in,
                              void* d_out, int out_size) {
    const float* infer = (const float*)d_in[0];
    const float* ref   = (const float*)d_in[1];
    detail_kernel<<<NBLOCKS, WPB * 32>>>(infer, ref, (float*)d_out);
}